// round 6
// baseline (speedup 1.0000x reference)
#include <cuda_runtime.h>
#include <cstdint>

#define N_ENT   100000
#define DIMK    1024
#define BATCH   1024
#define K2      2048
#define MT      128
#define NT      256
#define KT      32
#define NIT     (K2 / KT)       // 64
#define STAGES  3
#define STAGE_BYTES 49152       // A 16KB + B 32KB
#define SMEM_TOTAL (STAGES * STAGE_BYTES)   // 147456
#define A_OFF   0
#define B_OFF   16384

__device__ float g_A[BATCH * K2];   // rotated, tf32-rounded A [1024 x 2048]

// ---------------- helpers ----------------
__device__ __forceinline__ uint32_t smem_u32(const void* p) {
    uint32_t a;
    asm("{ .reg .u64 t; cvta.to.shared.u64 t, %1; cvt.u32.u64 %0, t; }" : "=r"(a) : "l"(p));
    return a;
}
__device__ __forceinline__ float tf32_rna(float x) {
    uint32_t u;
    asm("cvt.rna.tf32.f32 %0, %1;" : "=r"(u) : "f"(x));
    return __uint_as_float(u);
}
__device__ __forceinline__ uint32_t tf32_rna_u(uint32_t x) {
    uint32_t u;
    asm("cvt.rna.tf32.f32 %0, %1;" : "=r"(u) : "f"(__uint_as_float(x)));
    return u;
}
__device__ __forceinline__ void cp_async16(uint32_t dst, const void* src, uint32_t src_bytes) {
    asm volatile("cp.async.cg.shared.global [%0], [%1], 16, %2;"
                 :: "r"(dst), "l"(src), "r"(src_bytes) : "memory");
}
__device__ __forceinline__ void cp_commit() {
    asm volatile("cp.async.commit_group;" ::: "memory");
}
template <int N>
__device__ __forceinline__ void cp_wait() {
    asm volatile("cp.async.wait_group %0;" :: "n"(N) : "memory");
}
__device__ __forceinline__ void ldsm_x4(uint32_t& r0, uint32_t& r1, uint32_t& r2, uint32_t& r3,
                                        uint32_t addr) {
    asm volatile("ldmatrix.sync.aligned.m8n8.x4.shared.b16 {%0,%1,%2,%3}, [%4];"
                 : "=r"(r0), "=r"(r1), "=r"(r2), "=r"(r3) : "r"(addr));
}
__device__ __forceinline__ void mma_tf32(float* c, const uint32_t* a, const uint32_t* b) {
    asm volatile(
        "mma.sync.aligned.m16n8k8.row.col.f32.tf32.tf32.f32 "
        "{%0,%1,%2,%3}, {%4,%5,%6,%7}, {%8,%9}, {%0,%1,%2,%3};"
        : "+f"(c[0]), "+f"(c[1]), "+f"(c[2]), "+f"(c[3])
        : "r"(a[0]), "r"(a[1]), "r"(a[2]), "r"(a[3]), "r"(b[0]), "r"(b[1]));
}

// swizzled float offset within a tile that has 32-float rows
__device__ __forceinline__ uint32_t swz(uint32_t row, uint32_t col) {
    return row * 32 + ((col + (row << 2)) & 31);
}

// ---------------- prep: gather + complex rotation -> g_A (tf32-rounded) ----------------
__global__ void rotate_prep(const int* __restrict__ e1, const int* __restrict__ r,
                            const float* __restrict__ ent_re, const float* __restrict__ ent_im,
                            const float* __restrict__ rel_phase) {
    int b = blockIdx.x;
    int e = e1[b];
    int rr = r[b];
    const float* hre = ent_re + (size_t)e * DIMK;
    const float* him = ent_im + (size_t)e * DIMK;
    const float* ph = rel_phase + (size_t)rr * DIMK;
    for (int d = threadIdx.x; d < DIMK; d += blockDim.x) {
        float s, c;
        sincosf(ph[d], &s, &c);
        float a = hre[d], bb = him[d];
        g_A[b * K2 + d]        = tf32_rna(a * c - bb * s);   // score_re
        g_A[b * K2 + DIMK + d] = tf32_rna(a * s + bb * c);   // score_im
    }
}

// ---------------- main GEMM ----------------
__global__ void __launch_bounds__(256, 1)
rotate_gemm(const float* __restrict__ ent_re, const float* __restrict__ ent_im,
            float* __restrict__ out) {
    extern __shared__ char smem[];
    const uint32_t sbase = smem_u32(smem);
    const int tid = threadIdx.x;
    const int w = tid >> 5;
    const int l = tid & 31;
    const int wm = w & 1;            // 0..1  -> 64-row slice
    const int wn = w >> 1;           // 0..3  -> 64-col slice
    const int m0 = blockIdx.x * MT;  // 8 m-tiles, fastest dim
    const int n0 = blockIdx.y * NT;  // 391 n-tiles

    const float* gA = g_A;

    // ldmatrix lane geometry
    const int t = l >> 3;
    const int rA = (t & 1) * 8 + (l & 7);   // A: tile row within 16
    const int cA = (t >> 1) * 4;            // A: k sub-offset
    const int nB = (t >> 1) * 8 + (l & 7);  // B: n row within 16
    const int cB = (t & 1) * 4;             // B: k sub-offset

    float acc[4][8][4];
#pragma unroll
    for (int i = 0; i < 4; ++i)
#pragma unroll
        for (int j = 0; j < 8; ++j)
#pragma unroll
            for (int q = 0; q < 4; ++q) acc[i][j][q] = 0.f;

    // per-thread load assignment (16B chunks, 32-float rows -> 8 chunks/row)
    // A tile: 128 rows -> 1024 chunks (4/thread); B tile: 256 rows -> 2048 chunks (8/thread)
    auto load_stage = [&](int it) {
        const int kk = it * KT;
        const uint32_t sa = sbase + (it % STAGES) * STAGE_BYTES + A_OFF;
        const uint32_t sb = sbase + (it % STAGES) * STAGE_BYTES + B_OFF;
#pragma unroll
        for (int i = 0; i < 4; ++i) {
            int c = tid + 256 * i;
            int row = c >> 3, kc = c & 7;
            const float* src = gA + (size_t)(m0 + row) * K2 + kk + kc * 4;
            cp_async16(sa + swz(row, kc * 4) * 4, src, 16);
        }
        const float* bbase = (kk < DIMK) ? ent_re : ent_im;
        const int kkl = kk & (DIMK - 1);
#pragma unroll
        for (int i = 0; i < 8; ++i) {
            int c = tid + 256 * i;
            int row = c >> 3, kc = c & 7;
            int n = n0 + row;
            int ok = (n < N_ENT);
            const float* src = bbase + (size_t)(ok ? n : 0) * DIMK + kkl + kc * 4;
            cp_async16(sb + swz(row, kc * 4) * 4, src, ok ? 16u : 0u);
        }
        cp_commit();
    };

    load_stage(0);
    load_stage(1);

    for (int it = 0; it < NIT; ++it) {
        if (it + 2 < NIT) {
            load_stage(it + 2);
            cp_wait<2>();
        } else if (it + 1 < NIT) {
            cp_wait<1>();
        } else {
            cp_wait<0>();
        }
        __syncthreads();

        const uint32_t sa = sbase + (it % STAGES) * STAGE_BYTES + A_OFF;
        const uint32_t sb = sbase + (it % STAGES) * STAGE_BYTES + B_OFF;

#pragma unroll
        for (int ks = 0; ks < 4; ++ks) {
            const int kb = ks * 8;
            uint32_t a[4][4];
#pragma unroll
            for (int i = 0; i < 4; ++i) {
                int row = wm * 64 + i * 16 + rA;
                ldsm_x4(a[i][0], a[i][1], a[i][2], a[i][3],
                        sa + swz(row, kb + cA) * 4);
            }
            uint32_t b[8][2];
#pragma unroll
            for (int jp = 0; jp < 4; ++jp) {
                int row = wn * 64 + jp * 16 + nB;
                uint32_t b0, b1, b2, b3;
                ldsm_x4(b0, b1, b2, b3, sb + swz(row, kb + cB) * 4);
                b[2 * jp][0]     = tf32_rna_u(b0);
                b[2 * jp][1]     = tf32_rna_u(b1);
                b[2 * jp + 1][0] = tf32_rna_u(b2);
                b[2 * jp + 1][1] = tf32_rna_u(b3);
            }
#pragma unroll
            for (int i = 0; i < 4; ++i)
#pragma unroll
                for (int j = 0; j < 8; ++j) mma_tf32(acc[i][j], a[i], b[j]);
        }
        __syncthreads();   // guard smem buffer reuse by next stage's cp.async
    }

    // epilogue: float2 stores, cols guarded against N_ENT
#pragma unroll
    for (int i = 0; i < 4; ++i) {
        int row0 = m0 + wm * 64 + i * 16 + (l >> 2);
        int row1 = row0 + 8;
#pragma unroll
        for (int j = 0; j < 8; ++j) {
            int col = n0 + wn * 64 + j * 8 + (l & 3) * 2;
            if (col < N_ENT) {
                *(float2*)(out + (size_t)row0 * N_ENT + col) =
                    make_float2(acc[i][j][0], acc[i][j][1]);
                *(float2*)(out + (size_t)row1 * N_ENT + col) =
                    make_float2(acc[i][j][2], acc[i][j][3]);
            }
        }
    }
}

// ---------------- launch ----------------
extern "C" void kernel_launch(void* const* d_in, const int* in_sizes, int n_in,
                              void* d_out, int out_size) {
    const int* e1 = (const int*)d_in[0];
    const int* r = (const int*)d_in[1];
    const float* ent_re = (const float*)d_in[2];
    const float* ent_im = (const float*)d_in[3];
    const float* rel_phase = (const float*)d_in[4];
    float* out = (float*)d_out;

    rotate_prep<<<BATCH, 256>>>(e1, r, ent_re, ent_im, rel_phase);

    cudaFuncSetAttribute(rotate_gemm, cudaFuncAttributeMaxDynamicSharedMemorySize, SMEM_TOTAL);
    dim3 grid(BATCH / MT, (N_ENT + NT - 1) / NT);   // (8, 391)
    rotate_gemm<<<grid, 256, SMEM_TOTAL>>>(ent_re, ent_im, out);
}

// round 8
// speedup vs baseline: 1.2007x; 1.2007x over previous
#include <cuda_runtime.h>
#include <cstdint>

#define N_ENT   100000
#define DIMK    1024
#define BATCH   1024
#define K2      2048
#define MT      128
#define NT      256
#define KT      32
#define NIT     (K2 / KT)       // 64
#define STAGES  4
#define STAGE_BYTES 49152       // A 16KB + B 32KB
#define SMEM_TOTAL (STAGES * STAGE_BYTES)   // 196608
#define A_OFF   0
#define B_OFF   16384
#define NTHREADS 512

__device__ float g_A[BATCH * K2];   // rotated, tf32-rounded A [1024 x 2048]

// ---------------- helpers ----------------
__device__ __forceinline__ uint32_t smem_u32(const void* p) {
    uint32_t a;
    asm("{ .reg .u64 t; cvta.to.shared.u64 t, %1; cvt.u32.u64 %0, t; }" : "=r"(a) : "l"(p));
    return a;
}
__device__ __forceinline__ float tf32_rna(float x) {
    uint32_t u;
    asm("cvt.rna.tf32.f32 %0, %1;" : "=r"(u) : "f"(x));
    return __uint_as_float(u);
}
__device__ __forceinline__ uint32_t tf32_rna_u(uint32_t x) {
    uint32_t u;
    asm("cvt.rna.tf32.f32 %0, %1;" : "=r"(u) : "f"(__uint_as_float(x)));
    return u;
}
__device__ __forceinline__ void cp_async16(uint32_t dst, const void* src, uint32_t src_bytes) {
    asm volatile("cp.async.cg.shared.global [%0], [%1], 16, %2;"
                 :: "r"(dst), "l"(src), "r"(src_bytes) : "memory");
}
__device__ __forceinline__ void cp_commit() {
    asm volatile("cp.async.commit_group;" ::: "memory");
}
template <int N>
__device__ __forceinline__ void cp_wait() {
    asm volatile("cp.async.wait_group %0;" :: "n"(N) : "memory");
}
__device__ __forceinline__ void ldsm_x4(uint32_t& r0, uint32_t& r1, uint32_t& r2, uint32_t& r3,
                                        uint32_t addr) {
    asm volatile("ldmatrix.sync.aligned.m8n8.x4.shared.b16 {%0,%1,%2,%3}, [%4];"
                 : "=r"(r0), "=r"(r1), "=r"(r2), "=r"(r3) : "r"(addr));
}
__device__ __forceinline__ void mma_tf32(float* c, const uint32_t* a, const uint32_t* b) {
    asm volatile(
        "mma.sync.aligned.m16n8k8.row.col.f32.tf32.tf32.f32 "
        "{%0,%1,%2,%3}, {%4,%5,%6,%7}, {%8,%9}, {%0,%1,%2,%3};"
        : "+f"(c[0]), "+f"(c[1]), "+f"(c[2]), "+f"(c[3])
        : "r"(a[0]), "r"(a[1]), "r"(a[2]), "r"(a[3]), "r"(b[0]), "r"(b[1]));
}

// swizzled float offset within a tile that has 32-float rows
__device__ __forceinline__ uint32_t swz(uint32_t row, uint32_t col) {
    return row * 32 + ((col + (row << 2)) & 31);
}

// ---------------- prep: gather + complex rotation -> g_A (tf32-rounded) ----------------
__global__ void rotate_prep(const int* __restrict__ e1, const int* __restrict__ r,
                            const float* __restrict__ ent_re, const float* __restrict__ ent_im,
                            const float* __restrict__ rel_phase) {
    int b = blockIdx.x;
    int e = e1[b];
    int rr = r[b];
    const float* hre = ent_re + (size_t)e * DIMK;
    const float* him = ent_im + (size_t)e * DIMK;
    const float* ph = rel_phase + (size_t)rr * DIMK;
    for (int d = threadIdx.x; d < DIMK; d += blockDim.x) {
        float s, c;
        sincosf(ph[d], &s, &c);
        float a = hre[d], bb = him[d];
        g_A[b * K2 + d]        = tf32_rna(a * c - bb * s);   // score_re
        g_A[b * K2 + DIMK + d] = tf32_rna(a * s + bb * c);   // score_im
    }
}

// ---------------- main GEMM: 512 threads, warp tile 32x64, 4-stage pipeline ----------------
__global__ void __launch_bounds__(NTHREADS, 1)
rotate_gemm(const float* __restrict__ ent_re, const float* __restrict__ ent_im,
            float* __restrict__ out) {
    extern __shared__ char smem[];
    const uint32_t sbase = smem_u32(smem);
    const int tid = threadIdx.x;
    const int w = tid >> 5;
    const int l = tid & 31;
    const int wm = w & 3;            // 0..3 -> 32-row slice
    const int wn = w >> 2;           // 0..3 -> 64-col slice
    const int m0 = blockIdx.x * MT;  // 8 m-tiles, fastest dim
    const int n0 = blockIdx.y * NT;  // 391 n-tiles

    const float* gA = g_A;

    // ldmatrix lane geometry
    const int t = l >> 3;
    const int rA = (t & 1) * 8 + (l & 7);   // A: tile row within 16
    const int cA = (t >> 1) * 4;            // A: k sub-offset
    const int nB = (t >> 1) * 8 + (l & 7);  // B: n row within 16
    const int cB = (t & 1) * 4;             // B: k sub-offset

    float acc[2][8][4];
#pragma unroll
    for (int i = 0; i < 2; ++i)
#pragma unroll
        for (int j = 0; j < 8; ++j)
#pragma unroll
            for (int q = 0; q < 4; ++q) acc[i][j][q] = 0.f;

    // per-thread load assignment (16B chunks, 32-float rows -> 8 chunks/row)
    // A tile: 128 rows -> 1024 chunks (2/thread); B tile: 256 rows -> 2048 chunks (4/thread)
    auto load_stage = [&](int it) {
        const int kk = it * KT;
        const uint32_t sa = sbase + (it % STAGES) * STAGE_BYTES + A_OFF;
        const uint32_t sb = sbase + (it % STAGES) * STAGE_BYTES + B_OFF;
#pragma unroll
        for (int i = 0; i < 2; ++i) {
            int c = tid + NTHREADS * i;
            int row = c >> 3, kc = c & 7;
            const float* src = gA + (size_t)(m0 + row) * K2 + kk + kc * 4;
            cp_async16(sa + swz(row, kc * 4) * 4, src, 16);
        }
        const float* bbase = (kk < DIMK) ? ent_re : ent_im;
        const int kkl = kk & (DIMK - 1);
#pragma unroll
        for (int i = 0; i < 4; ++i) {
            int c = tid + NTHREADS * i;
            int row = c >> 3, kc = c & 7;
            int n = n0 + row;
            int ok = (n < N_ENT);
            const float* src = bbase + (size_t)(ok ? n : 0) * DIMK + kkl + kc * 4;
            cp_async16(sb + swz(row, kc * 4) * 4, src, ok ? 16u : 0u);
        }
        cp_commit();
    };

    load_stage(0);
    load_stage(1);
    load_stage(2);

    for (int it = 0; it < NIT; ++it) {
        if (it + 3 < NIT) {
            load_stage(it + 3);
            cp_wait<3>();
        } else if (it + 2 < NIT) {
            cp_wait<2>();
        } else if (it + 1 < NIT) {
            cp_wait<1>();
        } else {
            cp_wait<0>();
        }
        __syncthreads();

        const uint32_t sa = sbase + (it % STAGES) * STAGE_BYTES + A_OFF;
        const uint32_t sb = sbase + (it % STAGES) * STAGE_BYTES + B_OFF;

#pragma unroll
        for (int ks = 0; ks < 4; ++ks) {
            const int kb = ks * 8;
            uint32_t a[2][4];
#pragma unroll
            for (int i = 0; i < 2; ++i) {
                int row = wm * 32 + i * 16 + rA;
                ldsm_x4(a[i][0], a[i][1], a[i][2], a[i][3],
                        sa + swz(row, kb + cA) * 4);
            }
            uint32_t b[8][2];
#pragma unroll
            for (int jp = 0; jp < 4; ++jp) {
                int row = wn * 64 + jp * 16 + nB;
                uint32_t b0, b1, b2, b3;
                ldsm_x4(b0, b1, b2, b3, sb + swz(row, kb + cB) * 4);
                b[2 * jp][0]     = tf32_rna_u(b0);
                b[2 * jp][1]     = tf32_rna_u(b1);
                b[2 * jp + 1][0] = tf32_rna_u(b2);
                b[2 * jp + 1][1] = tf32_rna_u(b3);
            }
#pragma unroll
            for (int i = 0; i < 2; ++i)
#pragma unroll
                for (int j = 0; j < 8; ++j) mma_tf32(acc[i][j], a[i], b[j]);
        }
        __syncthreads();   // guard smem buffer reuse by the next load
    }

    // epilogue: float2 stores, cols guarded against N_ENT
#pragma unroll
    for (int i = 0; i < 2; ++i) {
        int row0 = m0 + wm * 32 + i * 16 + (l >> 2);
        int row1 = row0 + 8;
#pragma unroll
        for (int j = 0; j < 8; ++j) {
            int col = n0 + wn * 64 + j * 8 + (l & 3) * 2;
            if (col < N_ENT) {
                *(float2*)(out + (size_t)row0 * N_ENT + col) =
                    make_float2(acc[i][j][0], acc[i][j][1]);
                *(float2*)(out + (size_t)row1 * N_ENT + col) =
                    make_float2(acc[i][j][2], acc[i][j][3]);
            }
        }
    }
}

// ---------------- launch ----------------
extern "C" void kernel_launch(void* const* d_in, const int* in_sizes, int n_in,
                              void* d_out, int out_size) {
    const int* e1 = (const int*)d_in[0];
    const int* r = (const int*)d_in[1];
    const float* ent_re = (const float*)d_in[2];
    const float* ent_im = (const float*)d_in[3];
    const float* rel_phase = (const float*)d_in[4];
    float* out = (float*)d_out;

    rotate_prep<<<BATCH, 256>>>(e1, r, ent_re, ent_im, rel_phase);

    cudaFuncSetAttribute(rotate_gemm, cudaFuncAttributeMaxDynamicSharedMemorySize, SMEM_TOTAL);
    dim3 grid(BATCH / MT, (N_ENT + NT - 1) / NT);   // (8, 391)
    rotate_gemm<<<grid, NTHREADS, SMEM_TOTAL>>>(ent_re, ent_im, out);
}